// round 7
// baseline (speedup 1.0000x reference)
#include <cuda_runtime.h>

#define NN 30000
#define EE 480000

// ---- device scratch (no allocs allowed) ----
__device__ float4 g_aggA[NN * 32];   // per node, 32 ch x {s_a, v_a.xyz}
__device__ float4 g_aggB[NN * 32];   // per node, 32 ch x {s_b, v_b.xyz}
__device__ float4 g_xv[NN * 32];     // {x0, y0, y1, y2} per (node, ch)
__device__ int    g_count[NN];
__device__ int    g_offset[NN + 1];
__device__ int    g_cursor[NN];
__device__ int    g_dsts[EE];        // sorted order
__device__ float  g_h[EE * 8];       // sorted order
__device__ float4 g_sh4[EE];         // sorted order

// ---------------------------------------------------------------------------
// xv = {node_s @ W1_0, einsum(node_v, W1_1)} * inv_m, packed. Zeroes g_count.
__global__ void node_pre_kernel(const float* __restrict__ node_s,
                                const float* __restrict__ node_v,
                                const float* __restrict__ W1_0,
                                const float* __restrict__ W1_1) {
    __shared__ float w0s[1024], w1s[1024];
    for (int i = threadIdx.x; i < 1024; i += blockDim.x) {
        w0s[i] = W1_0[i];
        w1s[i] = W1_1[i];
    }
    __syncthreads();
    int warp = (blockIdx.x * blockDim.x + threadIdx.x) >> 5;
    int lane = threadIdx.x & 31;
    if (warp >= NN) return;
    if (lane == 0) g_count[warp] = 0;

    float s  = node_s[warp * 32 + lane];
    float v0 = node_v[warp * 96 + lane * 3 + 0];
    float v1 = node_v[warp * 96 + lane * 3 + 1];
    float v2 = node_v[warp * 96 + lane * 3 + 2];

    float x0 = 0.f, a0 = 0.f, a1 = 0.f, a2 = 0.f;
#pragma unroll
    for (int u = 0; u < 32; u++) {
        float su  = __shfl_sync(0xffffffffu, s,  u);
        float vu0 = __shfl_sync(0xffffffffu, v0, u);
        float vu1 = __shfl_sync(0xffffffffu, v1, u);
        float vu2 = __shfl_sync(0xffffffffu, v2, u);
        float w0 = w0s[u * 32 + lane];
        float w1 = w1s[u * 32 + lane];
        x0 = fmaf(su, w0, x0);
        a0 = fmaf(vu0, w1, a0);
        a1 = fmaf(vu1, w1, a1);
        a2 = fmaf(vu2, w1, a2);
    }
    const float inv_m = 0.17677669529663687f;  // 1/sqrt(32)
    g_xv[warp * 32 + lane] = make_float4(x0 * inv_m, a0 * inv_m,
                                         a1 * inv_m, a2 * inv_m);
}

// ---------------------------------------------------------------------------
__global__ void hist_kernel(const int* __restrict__ edge_src) {
    int i = blockIdx.x * blockDim.x + threadIdx.x;
    if (i < EE) atomicAdd(&g_count[edge_src[i]], 1);
}

__global__ void scan_kernel() {
    __shared__ int ps[1024];
    int tid = threadIdx.x;
    const int CH = 30;  // 1024*30 >= NN
    int base = tid * CH;
    int s = 0;
    for (int i = 0; i < CH; i++) {
        int idx = base + i;
        if (idx < NN) s += g_count[idx];
    }
    ps[tid] = s;
    __syncthreads();
    for (int off = 1; off < 1024; off <<= 1) {
        int t = (tid >= off) ? ps[tid - off] : 0;
        __syncthreads();
        ps[tid] += t;
        __syncthreads();
    }
    int run = ps[tid] - s;
    for (int i = 0; i < CH; i++) {
        int idx = base + i;
        if (idx < NN) {
            g_offset[idx] = run;
            g_cursor[idx] = run;
            run += g_count[idx];
        }
    }
    if (tid == 0) g_offset[NN] = EE;
}

// ---------------------------------------------------------------------------
// Fused scatter + h MLP: thread per original edge; compute slot p, write
// dst/h/sh directly at the scattered (sorted) position.
__global__ void scatter_h_kernel(const int*   __restrict__ edge_src,
                                 const int*   __restrict__ edge_dst,
                                 const float* __restrict__ edge_scalars,
                                 const float* __restrict__ edge_attr,
                                 const float* __restrict__ Wfc1) {
    __shared__ float fc1s[64];
    if (threadIdx.x < 64) fc1s[threadIdx.x] = Wfc1[threadIdx.x];
    __syncthreads();
    int i = blockIdx.x * blockDim.x + threadIdx.x;
    if (i >= EE) return;

    int s = edge_src[i];
    int p = atomicAdd(&g_cursor[s], 1);
    g_dsts[p] = edge_dst[i];

    float4 e0 = ((const float4*)(edge_scalars + i * 8))[0];
    float4 e1 = ((const float4*)(edge_scalars + i * 8))[1];
    float es[8] = {e0.x, e0.y, e0.z, e0.w, e1.x, e1.y, e1.z, e1.w};

    const float inv8 = 0.35355339059327373f;  // 1/sqrt(8)
    float h[8];
#pragma unroll
    for (int j = 0; j < 8; j++) {
        float acc = 0.f;
#pragma unroll
        for (int k = 0; k < 8; k++)
            acc = fmaf(es[k], fc1s[k * 8 + j], acc);
        acc *= inv8;
        float ex = __expf(-fabsf(acc));
        h[j] = fmaxf(acc, 0.f) + log1pf(ex) - 0.6931471805599453f;
    }
    ((float4*)(g_h + p * 8))[0] = make_float4(h[0], h[1], h[2], h[3]);
    ((float4*)(g_h + p * 8))[1] = make_float4(h[4], h[5], h[6], h[7]);
    g_sh4[p] = *(const float4*)(edge_attr + i * 4);
}

// ---------------------------------------------------------------------------
__device__ __forceinline__ void edge_compute(
    float4 h0, float4 h1, float4 sh, float4 xv,
    const float* __restrict__ fc2s, int lane,
    float& aA0, float& aA1, float& aA2, float& aA3,
    float& aB0, float& aB1, float& aB2, float& aB3)
{
    const float inv8 = 0.35355339059327373f;
    const float INV_SQRT3 = 0.5773502691896258f;

    const float* r0 = &fc2s[lane];
    float w00 = h0.x * r0[0];
    w00 = fmaf(h0.y, r0[128], w00); w00 = fmaf(h0.z, r0[256], w00);
    w00 = fmaf(h0.w, r0[384], w00); w00 = fmaf(h1.x, r0[512], w00);
    w00 = fmaf(h1.y, r0[640], w00); w00 = fmaf(h1.z, r0[768], w00);
    w00 = fmaf(h1.w, r0[896], w00);
    const float* r1 = r0 + 32;
    float w01 = h0.x * r1[0];
    w01 = fmaf(h0.y, r1[128], w01); w01 = fmaf(h0.z, r1[256], w01);
    w01 = fmaf(h0.w, r1[384], w01); w01 = fmaf(h1.x, r1[512], w01);
    w01 = fmaf(h1.y, r1[640], w01); w01 = fmaf(h1.z, r1[768], w01);
    w01 = fmaf(h1.w, r1[896], w01);
    const float* r2 = r0 + 64;
    float w10 = h0.x * r2[0];
    w10 = fmaf(h0.y, r2[128], w10); w10 = fmaf(h0.z, r2[256], w10);
    w10 = fmaf(h0.w, r2[384], w10); w10 = fmaf(h1.x, r2[512], w10);
    w10 = fmaf(h1.y, r2[640], w10); w10 = fmaf(h1.z, r2[768], w10);
    w10 = fmaf(h1.w, r2[896], w10);
    const float* r3 = r0 + 96;
    float w11 = h0.x * r3[0];
    w11 = fmaf(h0.y, r3[128], w11); w11 = fmaf(h0.z, r3[256], w11);
    w11 = fmaf(h0.w, r3[384], w11); w11 = fmaf(h1.x, r3[512], w11);
    w11 = fmaf(h1.y, r3[640], w11); w11 = fmaf(h1.z, r3[768], w11);
    w11 = fmaf(h1.w, r3[896], w11);
    w00 *= inv8; w01 *= inv8; w10 *= inv8; w11 *= inv8;

    float x0 = xv.x, y0 = xv.y, y1 = xv.z, y2 = xv.w;
    float s_a = w00 * x0 * sh.x;
    float dot = fmaf(y0, sh.y, fmaf(y1, sh.z, y2 * sh.w));
    float s_b = w11 * dot * INV_SQRT3;
    float p = w01 * x0;
    float q = w10 * sh.x;

    aA0 += s_a;              aA1 = fmaf(p, sh.y, aA1);
    aA2 = fmaf(p, sh.z, aA2); aA3 = fmaf(p, sh.w, aA3);
    aB0 += s_b;              aB1 = fmaf(q, y0, aB1);
    aB2 = fmaf(q, y1, aB2);   aB3 = fmaf(q, y2, aB3);
}

#define LOADE(H0, H1, SH, XV, IDX) {                       \
    H0 = ((const float4*)(g_h + (IDX) * 8))[0];            \
    H1 = ((const float4*)(g_h + (IDX) * 8))[1];            \
    SH = g_sh4[IDX];                                       \
    int _d = g_dsts[IDX];                                  \
    XV = g_xv[_d * 32 + lane]; }

// Warp per src node; depth-2 software pipeline; no atomics.
__global__ __launch_bounds__(256)
void edge_agg3_kernel(const float* __restrict__ Wfc2) {
    __shared__ float fc2s[1024];
    for (int i = threadIdx.x; i < 1024; i += blockDim.x) fc2s[i] = Wfc2[i];
    __syncthreads();

    int n = blockIdx.x * 8 + (threadIdx.x >> 5);
    int lane = threadIdx.x & 31;
    if (n >= NN) return;

    int beg = g_offset[n], end = g_offset[n + 1];

    float aA0 = 0.f, aA1 = 0.f, aA2 = 0.f, aA3 = 0.f;
    float aB0 = 0.f, aB1 = 0.f, aB2 = 0.f, aB3 = 0.f;

    float4 h0a, h1a, sha, xva, h0b, h1b, shb, xvb;
    h0a = h1a = sha = xva = make_float4(0.f, 0.f, 0.f, 0.f);
    h0b = h1b = shb = xvb = h0a;

    if (beg < end)     LOADE(h0a, h1a, sha, xva, beg);
    if (beg + 1 < end) LOADE(h0b, h1b, shb, xvb, beg + 1);

    int i = beg;
    for (; i + 2 <= end; i += 2) {
        float4 c0 = h0a, c1 = h1a, cs = sha, cx = xva;
        float4 d0 = h0b, d1 = h1b, ds = shb, dx = xvb;
        if (i + 2 < end) LOADE(h0a, h1a, sha, xva, i + 2);
        if (i + 3 < end) LOADE(h0b, h1b, shb, xvb, i + 3);
        edge_compute(c0, c1, cs, cx, fc2s, lane,
                     aA0, aA1, aA2, aA3, aB0, aB1, aB2, aB3);
        edge_compute(d0, d1, ds, dx, fc2s, lane,
                     aA0, aA1, aA2, aA3, aB0, aB1, aB2, aB3);
    }
    if (i < end)
        edge_compute(h0a, h1a, sha, xva, fc2s, lane,
                     aA0, aA1, aA2, aA3, aB0, aB1, aB2, aB3);

    g_aggA[n * 32 + lane] = make_float4(aA0, aA1, aA2, aA3);
    g_aggB[n * 32 + lane] = make_float4(aB0, aB1, aB2, aB3);
}

// ---------------------------------------------------------------------------
// node_post4 (unchanged from R6): lane = channel w, 2 nodes per warp,
// Wsc in 64KB dynamic smem (3 blocks/SM); W2 via L1 LDG.
#define P4_W0LO 0
#define P4_W0HI 4096
#define P4_W1LO 8192
#define P4_W1HI 12288
#define P4_FLOATS 16384
#define P4_BYTES (P4_FLOATS * 4)
#define P4_TILES 1875

__global__ __launch_bounds__(256)
void node_post4_kernel(const float* __restrict__ node_s,
                       const float* __restrict__ node_v,
                       const float* __restrict__ node_attr,
                       const float* __restrict__ W2_0,
                       const float* __restrict__ W2_1,
                       const float* __restrict__ Wsc0,
                       const float* __restrict__ Wsc1,
                       float* __restrict__ out) {
    extern __shared__ float sm[];
    const float c_agg = 0.03125f;  // 1/sqrt(64)*1/sqrt(16)
    const float c_sc  = 0.0625f;   // 1/sqrt(32*8)
    int tid = threadIdx.x;

    for (int i = tid; i < 8192; i += 256) {
        int u = i >> 8, v = (i >> 5) & 7, w = i & 31;
        int base = (u * 32 + w) * 4 + (v & 3);
        int lo = (v < 4);
        sm[(lo ? P4_W0LO : P4_W0HI) + base] = Wsc0[i] * c_sc;
        sm[(lo ? P4_W1LO : P4_W1HI) + base] = Wsc1[i] * c_sc;
    }
    __syncthreads();

    int wid = tid >> 5, lane = tid & 31;

    for (int tile = blockIdx.x; tile < P4_TILES; tile += gridDim.x) {
        int n0 = tile * 16 + wid * 2;
        int n1 = n0 + 1;

        float s0 = node_s[n0 * 32 + lane];
        float s1 = node_s[n1 * 32 + lane];
        float v00 = node_v[n0 * 96 + lane * 3 + 0];
        float v01 = node_v[n0 * 96 + lane * 3 + 1];
        float v02 = node_v[n0 * 96 + lane * 3 + 2];
        float v10 = node_v[n1 * 96 + lane * 3 + 0];
        float v11 = node_v[n1 * 96 + lane * 3 + 1];
        float v12 = node_v[n1 * 96 + lane * 3 + 2];
        float4 a0lo = ((const float4*)(node_attr + n0 * 8))[0];
        float4 a0hi = ((const float4*)(node_attr + n0 * 8))[1];
        float4 a1lo = ((const float4*)(node_attr + n1 * 8))[0];
        float4 a1hi = ((const float4*)(node_attr + n1 * 8))[1];

        float accS0 = 0.f, aV00 = 0.f, aV01 = 0.f, aV02 = 0.f;
        float accS1 = 0.f, aV10 = 0.f, aV11 = 0.f, aV12 = 0.f;

#pragma unroll 4
        for (int u = 0; u < 32; u++) {
            float su0 = __shfl_sync(0xffffffffu, s0, u);
            float su1 = __shfl_sync(0xffffffffu, s1, u);
            float wv00 = __shfl_sync(0xffffffffu, v00, u);
            float wv01 = __shfl_sync(0xffffffffu, v01, u);
            float wv02 = __shfl_sync(0xffffffffu, v02, u);
            float wv10 = __shfl_sync(0xffffffffu, v10, u);
            float wv11 = __shfl_sync(0xffffffffu, v11, u);
            float wv12 = __shfl_sync(0xffffffffu, v12, u);

            int o = (u * 32 + lane) * 4;
            float4 c0 = *(const float4*)&sm[P4_W0LO + o];
            float4 c1 = *(const float4*)&sm[P4_W0HI + o];
            float4 d0 = *(const float4*)&sm[P4_W1LO + o];
            float4 d1 = *(const float4*)&sm[P4_W1HI + o];

            float A00 = a0lo.x * c0.x;
            A00 = fmaf(a0lo.y, c0.y, A00); A00 = fmaf(a0lo.z, c0.z, A00);
            A00 = fmaf(a0lo.w, c0.w, A00); A00 = fmaf(a0hi.x, c1.x, A00);
            A00 = fmaf(a0hi.y, c1.y, A00); A00 = fmaf(a0hi.z, c1.z, A00);
            A00 = fmaf(a0hi.w, c1.w, A00);
            float A01 = a1lo.x * c0.x;
            A01 = fmaf(a1lo.y, c0.y, A01); A01 = fmaf(a1lo.z, c0.z, A01);
            A01 = fmaf(a1lo.w, c0.w, A01); A01 = fmaf(a1hi.x, c1.x, A01);
            A01 = fmaf(a1hi.y, c1.y, A01); A01 = fmaf(a1hi.z, c1.z, A01);
            A01 = fmaf(a1hi.w, c1.w, A01);
            float A10 = a0lo.x * d0.x;
            A10 = fmaf(a0lo.y, d0.y, A10); A10 = fmaf(a0lo.z, d0.z, A10);
            A10 = fmaf(a0lo.w, d0.w, A10); A10 = fmaf(a0hi.x, d1.x, A10);
            A10 = fmaf(a0hi.y, d1.y, A10); A10 = fmaf(a0hi.z, d1.z, A10);
            A10 = fmaf(a0hi.w, d1.w, A10);
            float A11 = a1lo.x * d0.x;
            A11 = fmaf(a1lo.y, d0.y, A11); A11 = fmaf(a1lo.z, d0.z, A11);
            A11 = fmaf(a1lo.w, d0.w, A11); A11 = fmaf(a1hi.x, d1.x, A11);
            A11 = fmaf(a1hi.y, d1.y, A11); A11 = fmaf(a1hi.z, d1.z, A11);
            A11 = fmaf(a1hi.w, d1.w, A11);

            accS0 = fmaf(su0, A00, accS0);
            accS1 = fmaf(su1, A01, accS1);
            aV00 = fmaf(wv00, A10, aV00);
            aV01 = fmaf(wv01, A10, aV01);
            aV02 = fmaf(wv02, A10, aV02);
            aV10 = fmaf(wv10, A11, aV10);
            aV11 = fmaf(wv11, A11, aV11);
            aV12 = fmaf(wv12, A11, aV12);
        }

#pragma unroll 4
        for (int k = 0; k < 32; k++) {
            float4 qa = g_aggA[n0 * 32 + k];
            float4 qb = g_aggA[n1 * 32 + k];
            float t0 = W2_0[k * 32 + lane] * c_agg;
            float t1 = W2_1[k * 32 + lane] * c_agg;
            accS0 = fmaf(qa.x, t0, accS0);
            aV00 = fmaf(qa.y, t1, aV00);
            aV01 = fmaf(qa.z, t1, aV01);
            aV02 = fmaf(qa.w, t1, aV02);
            accS1 = fmaf(qb.x, t0, accS1);
            aV10 = fmaf(qb.y, t1, aV10);
            aV11 = fmaf(qb.z, t1, aV11);
            aV12 = fmaf(qb.w, t1, aV12);
        }
#pragma unroll 4
        for (int k = 0; k < 32; k++) {
            float4 qa = g_aggB[n0 * 32 + k];
            float4 qb = g_aggB[n1 * 32 + k];
            float t0 = W2_0[(32 + k) * 32 + lane] * c_agg;
            float t1 = W2_1[(32 + k) * 32 + lane] * c_agg;
            accS0 = fmaf(qa.x, t0, accS0);
            aV00 = fmaf(qa.y, t1, aV00);
            aV01 = fmaf(qa.z, t1, aV01);
            aV02 = fmaf(qa.w, t1, aV02);
            accS1 = fmaf(qb.x, t0, accS1);
            aV10 = fmaf(qb.y, t1, aV10);
            aV11 = fmaf(qb.z, t1, aV11);
            aV12 = fmaf(qb.w, t1, aV12);
        }

        out[n0 * 128 + lane] = accS0;
        out[n0 * 128 + 32 + lane * 3 + 0] = aV00;
        out[n0 * 128 + 32 + lane * 3 + 1] = aV01;
        out[n0 * 128 + 32 + lane * 3 + 2] = aV02;
        out[n1 * 128 + lane] = accS1;
        out[n1 * 128 + 32 + lane * 3 + 0] = aV10;
        out[n1 * 128 + 32 + lane * 3 + 1] = aV11;
        out[n1 * 128 + 32 + lane * 3 + 2] = aV12;
    }
}

// ---------------------------------------------------------------------------
extern "C" void kernel_launch(void* const* d_in, const int* in_sizes, int n_in,
                              void* d_out, int out_size) {
    const float* node_s       = (const float*)d_in[0];
    const float* node_v       = (const float*)d_in[1];
    const float* node_attr    = (const float*)d_in[2];
    const float* edge_attr    = (const float*)d_in[3];
    const float* edge_scalars = (const float*)d_in[4];
    const float* W1_0         = (const float*)d_in[5];
    const float* W1_1         = (const float*)d_in[6];
    const float* Wfc1         = (const float*)d_in[7];
    const float* Wfc2         = (const float*)d_in[8];
    const float* W2_0         = (const float*)d_in[9];
    const float* W2_1         = (const float*)d_in[10];
    const float* Wsc0         = (const float*)d_in[11];
    const float* Wsc1         = (const float*)d_in[12];
    const int*   edge_src     = (const int*)d_in[13];
    const int*   edge_dst     = (const int*)d_in[14];
    float* out = (float*)d_out;

    cudaFuncSetAttribute(node_post4_kernel,
                         cudaFuncAttributeMaxDynamicSharedMemorySize, P4_BYTES);

    node_pre_kernel<<<(NN * 32 + 255) / 256, 256>>>(node_s, node_v, W1_0, W1_1);
    hist_kernel<<<(EE + 255) / 256, 256>>>(edge_src);
    scan_kernel<<<1, 1024>>>();
    scatter_h_kernel<<<(EE + 255) / 256, 256>>>(edge_src, edge_dst,
                                                edge_scalars, edge_attr, Wfc1);
    edge_agg3_kernel<<<(NN + 7) / 8, 256>>>(Wfc2);
    node_post4_kernel<<<444, 256, P4_BYTES>>>(node_s, node_v, node_attr,
                                              W2_0, W2_1, Wsc0, Wsc1, out);
}

// round 8
// speedup vs baseline: 1.0446x; 1.0446x over previous
#include <cuda_runtime.h>

#define NN 30000
#define EE 480000

// ---- device scratch (no allocs allowed) ----
__device__ float4 g_aggA[NN * 32];   // per node, 32 ch x {s_a, v_a.xyz}
__device__ float4 g_aggB[NN * 32];   // per node, 32 ch x {s_b, v_b.xyz}
__device__ float4 g_xv[NN * 32];     // {x0, y0, y1, y2} per (node, ch)
__device__ int    g_count[NN];
__device__ int    g_offset[NN + 1];
__device__ int    g_cursor[NN];
__device__ int    g_dsts[EE];        // sorted order
__device__ float  g_h[EE * 8];       // sorted order
__device__ float4 g_sh4[EE];         // sorted order

// ---------------------------------------------------------------------------
// Fused node-pre (xv = packed {x0,y0,y1,y2}) + edge histogram.
// g_count is zeroed by a preceding memset node.
__global__ void pre_hist_kernel(const float* __restrict__ node_s,
                                const float* __restrict__ node_v,
                                const float* __restrict__ W1_0,
                                const float* __restrict__ W1_1,
                                const int*   __restrict__ edge_src) {
    __shared__ float w0s[1024], w1s[1024];
    for (int i = threadIdx.x; i < 1024; i += blockDim.x) {
        w0s[i] = W1_0[i];
        w1s[i] = W1_1[i];
    }
    __syncthreads();
    int tid = blockIdx.x * blockDim.x + threadIdx.x;
    if (tid < EE) atomicAdd(&g_count[edge_src[tid]], 1);

    int warp = tid >> 5;
    int lane = threadIdx.x & 31;
    if (warp >= NN) return;

    float s  = node_s[warp * 32 + lane];
    float v0 = node_v[warp * 96 + lane * 3 + 0];
    float v1 = node_v[warp * 96 + lane * 3 + 1];
    float v2 = node_v[warp * 96 + lane * 3 + 2];

    float x0 = 0.f, a0 = 0.f, a1 = 0.f, a2 = 0.f;
#pragma unroll
    for (int u = 0; u < 32; u++) {
        float su  = __shfl_sync(0xffffffffu, s,  u);
        float vu0 = __shfl_sync(0xffffffffu, v0, u);
        float vu1 = __shfl_sync(0xffffffffu, v1, u);
        float vu2 = __shfl_sync(0xffffffffu, v2, u);
        float w0 = w0s[u * 32 + lane];
        float w1 = w1s[u * 32 + lane];
        x0 = fmaf(su, w0, x0);
        a0 = fmaf(vu0, w1, a0);
        a1 = fmaf(vu1, w1, a1);
        a2 = fmaf(vu2, w1, a2);
    }
    const float inv_m = 0.17677669529663687f;  // 1/sqrt(32)
    g_xv[warp * 32 + lane] = make_float4(x0 * inv_m, a0 * inv_m,
                                         a1 * inv_m, a2 * inv_m);
}

// ---------------------------------------------------------------------------
__global__ void scan_kernel() {
    __shared__ int ps[1024];
    int tid = threadIdx.x;
    const int CH = 30;  // 1024*30 >= NN
    int base = tid * CH;
    int s = 0;
    for (int i = 0; i < CH; i++) {
        int idx = base + i;
        if (idx < NN) s += g_count[idx];
    }
    ps[tid] = s;
    __syncthreads();
    for (int off = 1; off < 1024; off <<= 1) {
        int t = (tid >= off) ? ps[tid - off] : 0;
        __syncthreads();
        ps[tid] += t;
        __syncthreads();
    }
    int run = ps[tid] - s;
    for (int i = 0; i < CH; i++) {
        int idx = base + i;
        if (idx < NN) {
            g_offset[idx] = run;
            g_cursor[idx] = run;
            run += g_count[idx];
        }
    }
    if (tid == 0) g_offset[NN] = EE;
}

// ---------------------------------------------------------------------------
// Fused scatter + h MLP.
__global__ void scatter_h_kernel(const int*   __restrict__ edge_src,
                                 const int*   __restrict__ edge_dst,
                                 const float* __restrict__ edge_scalars,
                                 const float* __restrict__ edge_attr,
                                 const float* __restrict__ Wfc1) {
    __shared__ float fc1s[64];
    if (threadIdx.x < 64) fc1s[threadIdx.x] = Wfc1[threadIdx.x];
    __syncthreads();
    int i = blockIdx.x * blockDim.x + threadIdx.x;
    if (i >= EE) return;

    int s = edge_src[i];
    int p = atomicAdd(&g_cursor[s], 1);
    g_dsts[p] = edge_dst[i];

    float4 e0 = ((const float4*)(edge_scalars + i * 8))[0];
    float4 e1 = ((const float4*)(edge_scalars + i * 8))[1];
    float es[8] = {e0.x, e0.y, e0.z, e0.w, e1.x, e1.y, e1.z, e1.w};

    const float inv8 = 0.35355339059327373f;  // 1/sqrt(8)
    float h[8];
#pragma unroll
    for (int j = 0; j < 8; j++) {
        float acc = 0.f;
#pragma unroll
        for (int k = 0; k < 8; k++)
            acc = fmaf(es[k], fc1s[k * 8 + j], acc);
        acc *= inv8;
        float ex = __expf(-fabsf(acc));
        h[j] = fmaxf(acc, 0.f) + log1pf(ex) - 0.6931471805599453f;
    }
    ((float4*)(g_h + p * 8))[0] = make_float4(h[0], h[1], h[2], h[3]);
    ((float4*)(g_h + p * 8))[1] = make_float4(h[4], h[5], h[6], h[7]);
    g_sh4[p] = *(const float4*)(edge_attr + i * 4);
}

// ---------------------------------------------------------------------------
__device__ __forceinline__ void edge_compute(
    float4 h0, float4 h1, float4 sh, float4 xv,
    const float* __restrict__ fc2s, int lane,
    float& aA0, float& aA1, float& aA2, float& aA3,
    float& aB0, float& aB1, float& aB2, float& aB3)
{
    const float inv8 = 0.35355339059327373f;
    const float INV_SQRT3 = 0.5773502691896258f;

    const float* r0 = &fc2s[lane];
    float w00 = h0.x * r0[0];
    w00 = fmaf(h0.y, r0[128], w00); w00 = fmaf(h0.z, r0[256], w00);
    w00 = fmaf(h0.w, r0[384], w00); w00 = fmaf(h1.x, r0[512], w00);
    w00 = fmaf(h1.y, r0[640], w00); w00 = fmaf(h1.z, r0[768], w00);
    w00 = fmaf(h1.w, r0[896], w00);
    const float* r1 = r0 + 32;
    float w01 = h0.x * r1[0];
    w01 = fmaf(h0.y, r1[128], w01); w01 = fmaf(h0.z, r1[256], w01);
    w01 = fmaf(h0.w, r1[384], w01); w01 = fmaf(h1.x, r1[512], w01);
    w01 = fmaf(h1.y, r1[640], w01); w01 = fmaf(h1.z, r1[768], w01);
    w01 = fmaf(h1.w, r1[896], w01);
    const float* r2 = r0 + 64;
    float w10 = h0.x * r2[0];
    w10 = fmaf(h0.y, r2[128], w10); w10 = fmaf(h0.z, r2[256], w10);
    w10 = fmaf(h0.w, r2[384], w10); w10 = fmaf(h1.x, r2[512], w10);
    w10 = fmaf(h1.y, r2[640], w10); w10 = fmaf(h1.z, r2[768], w10);
    w10 = fmaf(h1.w, r2[896], w10);
    const float* r3 = r0 + 96;
    float w11 = h0.x * r3[0];
    w11 = fmaf(h0.y, r3[128], w11); w11 = fmaf(h0.z, r3[256], w11);
    w11 = fmaf(h0.w, r3[384], w11); w11 = fmaf(h1.x, r3[512], w11);
    w11 = fmaf(h1.y, r3[640], w11); w11 = fmaf(h1.z, r3[768], w11);
    w11 = fmaf(h1.w, r3[896], w11);
    w00 *= inv8; w01 *= inv8; w10 *= inv8; w11 *= inv8;

    float x0 = xv.x, y0 = xv.y, y1 = xv.z, y2 = xv.w;
    float s_a = w00 * x0 * sh.x;
    float dot = fmaf(y0, sh.y, fmaf(y1, sh.z, y2 * sh.w));
    float s_b = w11 * dot * INV_SQRT3;
    float p = w01 * x0;
    float q = w10 * sh.x;

    aA0 += s_a;               aA1 = fmaf(p, sh.y, aA1);
    aA2 = fmaf(p, sh.z, aA2); aA3 = fmaf(p, sh.w, aA3);
    aB0 += s_b;               aB1 = fmaf(q, y0, aB1);
    aB2 = fmaf(q, y1, aB2);   aB3 = fmaf(q, y2, aB3);
}

// ---------------------------------------------------------------------------
// edge_agg4: TWO warps per node (halved serial run), lean pipeline:
// dst index prefetched depth-2, payload depth-1. Halves combined via smem.
__global__ __launch_bounds__(256)
void edge_agg4_kernel(const float* __restrict__ Wfc2) {
    __shared__ float fc2s[1024];
    __shared__ float4 sA[4][32], sB[4][32];
    for (int i = threadIdx.x; i < 1024; i += blockDim.x) fc2s[i] = Wfc2[i];

    int wid = threadIdx.x >> 5;          // 0..7
    int lane = threadIdx.x & 31;
    int slot = wid >> 1;                 // node slot in block, 0..3
    int half = wid & 1;
    int n = blockIdx.x * 4 + slot;       // NN = 30000 divisible by 4? 7500*4 ✓

    int nbeg = g_offset[n], nend = g_offset[n + 1];
    int len = nend - nbeg;
    int h1len = (len + 1) >> 1;
    int beg = nbeg + half * h1len;
    int end = half ? nend : (nbeg + h1len);

    float aA0 = 0.f, aA1 = 0.f, aA2 = 0.f, aA3 = 0.f;
    float aB0 = 0.f, aB1 = 0.f, aB2 = 0.f, aB3 = 0.f;

    __syncthreads();  // fc2s ready

    if (beg < end) {
        int last = end - 1;
        // prologue: index at depth 2, payload at depth 1
        int d_cur = g_dsts[beg];
        int d_nx  = g_dsts[min(beg + 1, last)];
        float4 xv_c = g_xv[d_cur * 32 + lane];
        float4 h0_c = ((const float4*)(g_h + beg * 8))[0];
        float4 h1_c = ((const float4*)(g_h + beg * 8))[1];
        float4 sh_c = g_sh4[beg];

        for (int i = beg; i < end; i++) {
            float4 h0 = h0_c, h1 = h1_c, sh = sh_c, xv = xv_c;
            // prefetch: index i+2, payload i+1
            int ip1 = min(i + 1, last);
            int ip2 = min(i + 2, last);
            int d_pf = g_dsts[ip2];
            xv_c = g_xv[d_nx * 32 + lane];
            h0_c = ((const float4*)(g_h + ip1 * 8))[0];
            h1_c = ((const float4*)(g_h + ip1 * 8))[1];
            sh_c = g_sh4[ip1];
            d_nx = d_pf;

            edge_compute(h0, h1, sh, xv, fc2s, lane,
                         aA0, aA1, aA2, aA3, aB0, aB1, aB2, aB3);
        }
    }

    // combine halves: half1 writes to smem, half0 adds + stores
    if (half) {
        sA[slot][lane] = make_float4(aA0, aA1, aA2, aA3);
        sB[slot][lane] = make_float4(aB0, aB1, aB2, aB3);
    }
    __syncthreads();
    if (!half) {
        float4 pa = sA[slot][lane];
        float4 pb = sB[slot][lane];
        g_aggA[n * 32 + lane] = make_float4(aA0 + pa.x, aA1 + pa.y,
                                            aA2 + pa.z, aA3 + pa.w);
        g_aggB[n * 32 + lane] = make_float4(aB0 + pb.x, aB1 + pb.y,
                                            aB2 + pb.z, aB3 + pb.w);
    }
}

// ---------------------------------------------------------------------------
// node_post4 (unchanged): lane = channel w, 2 nodes per warp,
// Wsc in 64KB dynamic smem (3 blocks/SM); W2 via L1 LDG.
#define P4_W0LO 0
#define P4_W0HI 4096
#define P4_W1LO 8192
#define P4_W1HI 12288
#define P4_FLOATS 16384
#define P4_BYTES (P4_FLOATS * 4)
#define P4_TILES 1875

__global__ __launch_bounds__(256)
void node_post4_kernel(const float* __restrict__ node_s,
                       const float* __restrict__ node_v,
                       const float* __restrict__ node_attr,
                       const float* __restrict__ W2_0,
                       const float* __restrict__ W2_1,
                       const float* __restrict__ Wsc0,
                       const float* __restrict__ Wsc1,
                       float* __restrict__ out) {
    extern __shared__ float sm[];
    const float c_agg = 0.03125f;  // 1/sqrt(64)*1/sqrt(16)
    const float c_sc  = 0.0625f;   // 1/sqrt(32*8)
    int tid = threadIdx.x;

    for (int i = tid; i < 8192; i += 256) {
        int u = i >> 8, v = (i >> 5) & 7, w = i & 31;
        int base = (u * 32 + w) * 4 + (v & 3);
        int lo = (v < 4);
        sm[(lo ? P4_W0LO : P4_W0HI) + base] = Wsc0[i] * c_sc;
        sm[(lo ? P4_W1LO : P4_W1HI) + base] = Wsc1[i] * c_sc;
    }
    __syncthreads();

    int wid = tid >> 5, lane = tid & 31;

    for (int tile = blockIdx.x; tile < P4_TILES; tile += gridDim.x) {
        int n0 = tile * 16 + wid * 2;
        int n1 = n0 + 1;

        float s0 = node_s[n0 * 32 + lane];
        float s1 = node_s[n1 * 32 + lane];
        float v00 = node_v[n0 * 96 + lane * 3 + 0];
        float v01 = node_v[n0 * 96 + lane * 3 + 1];
        float v02 = node_v[n0 * 96 + lane * 3 + 2];
        float v10 = node_v[n1 * 96 + lane * 3 + 0];
        float v11 = node_v[n1 * 96 + lane * 3 + 1];
        float v12 = node_v[n1 * 96 + lane * 3 + 2];
        float4 a0lo = ((const float4*)(node_attr + n0 * 8))[0];
        float4 a0hi = ((const float4*)(node_attr + n0 * 8))[1];
        float4 a1lo = ((const float4*)(node_attr + n1 * 8))[0];
        float4 a1hi = ((const float4*)(node_attr + n1 * 8))[1];

        float accS0 = 0.f, aV00 = 0.f, aV01 = 0.f, aV02 = 0.f;
        float accS1 = 0.f, aV10 = 0.f, aV11 = 0.f, aV12 = 0.f;

#pragma unroll 4
        for (int u = 0; u < 32; u++) {
            float su0 = __shfl_sync(0xffffffffu, s0, u);
            float su1 = __shfl_sync(0xffffffffu, s1, u);
            float wv00 = __shfl_sync(0xffffffffu, v00, u);
            float wv01 = __shfl_sync(0xffffffffu, v01, u);
            float wv02 = __shfl_sync(0xffffffffu, v02, u);
            float wv10 = __shfl_sync(0xffffffffu, v10, u);
            float wv11 = __shfl_sync(0xffffffffu, v11, u);
            float wv12 = __shfl_sync(0xffffffffu, v12, u);

            int o = (u * 32 + lane) * 4;
            float4 c0 = *(const float4*)&sm[P4_W0LO + o];
            float4 c1 = *(const float4*)&sm[P4_W0HI + o];
            float4 d0 = *(const float4*)&sm[P4_W1LO + o];
            float4 d1 = *(const float4*)&sm[P4_W1HI + o];

            float A00 = a0lo.x * c0.x;
            A00 = fmaf(a0lo.y, c0.y, A00); A00 = fmaf(a0lo.z, c0.z, A00);
            A00 = fmaf(a0lo.w, c0.w, A00); A00 = fmaf(a0hi.x, c1.x, A00);
            A00 = fmaf(a0hi.y, c1.y, A00); A00 = fmaf(a0hi.z, c1.z, A00);
            A00 = fmaf(a0hi.w, c1.w, A00);
            float A01 = a1lo.x * c0.x;
            A01 = fmaf(a1lo.y, c0.y, A01); A01 = fmaf(a1lo.z, c0.z, A01);
            A01 = fmaf(a1lo.w, c0.w, A01); A01 = fmaf(a1hi.x, c1.x, A01);
            A01 = fmaf(a1hi.y, c1.y, A01); A01 = fmaf(a1hi.z, c1.z, A01);
            A01 = fmaf(a1hi.w, c1.w, A01);
            float A10 = a0lo.x * d0.x;
            A10 = fmaf(a0lo.y, d0.y, A10); A10 = fmaf(a0lo.z, d0.z, A10);
            A10 = fmaf(a0lo.w, d0.w, A10); A10 = fmaf(a0hi.x, d1.x, A10);
            A10 = fmaf(a0hi.y, d1.y, A10); A10 = fmaf(a0hi.z, d1.z, A10);
            A10 = fmaf(a0hi.w, d1.w, A10);
            float A11 = a1lo.x * d0.x;
            A11 = fmaf(a1lo.y, d0.y, A11); A11 = fmaf(a1lo.z, d0.z, A11);
            A11 = fmaf(a1lo.w, d0.w, A11); A11 = fmaf(a1hi.x, d1.x, A11);
            A11 = fmaf(a1hi.y, d1.y, A11); A11 = fmaf(a1hi.z, d1.z, A11);
            A11 = fmaf(a1hi.w, d1.w, A11);

            accS0 = fmaf(su0, A00, accS0);
            accS1 = fmaf(su1, A01, accS1);
            aV00 = fmaf(wv00, A10, aV00);
            aV01 = fmaf(wv01, A10, aV01);
            aV02 = fmaf(wv02, A10, aV02);
            aV10 = fmaf(wv10, A11, aV10);
            aV11 = fmaf(wv11, A11, aV11);
            aV12 = fmaf(wv12, A11, aV12);
        }

#pragma unroll 4
        for (int k = 0; k < 32; k++) {
            float4 qa = g_aggA[n0 * 32 + k];
            float4 qb = g_aggA[n1 * 32 + k];
            float t0 = W2_0[k * 32 + lane] * c_agg;
            float t1 = W2_1[k * 32 + lane] * c_agg;
            accS0 = fmaf(qa.x, t0, accS0);
            aV00 = fmaf(qa.y, t1, aV00);
            aV01 = fmaf(qa.z, t1, aV01);
            aV02 = fmaf(qa.w, t1, aV02);
            accS1 = fmaf(qb.x, t0, accS1);
            aV10 = fmaf(qb.y, t1, aV10);
            aV11 = fmaf(qb.z, t1, aV11);
            aV12 = fmaf(qb.w, t1, aV12);
        }
#pragma unroll 4
        for (int k = 0; k < 32; k++) {
            float4 qa = g_aggB[n0 * 32 + k];
            float4 qb = g_aggB[n1 * 32 + k];
            float t0 = W2_0[(32 + k) * 32 + lane] * c_agg;
            float t1 = W2_1[(32 + k) * 32 + lane] * c_agg;
            accS0 = fmaf(qa.x, t0, accS0);
            aV00 = fmaf(qa.y, t1, aV00);
            aV01 = fmaf(qa.z, t1, aV01);
            aV02 = fmaf(qa.w, t1, aV02);
            accS1 = fmaf(qb.x, t0, accS1);
            aV10 = fmaf(qb.y, t1, aV10);
            aV11 = fmaf(qb.z, t1, aV11);
            aV12 = fmaf(qb.w, t1, aV12);
        }

        out[n0 * 128 + lane] = accS0;
        out[n0 * 128 + 32 + lane * 3 + 0] = aV00;
        out[n0 * 128 + 32 + lane * 3 + 1] = aV01;
        out[n0 * 128 + 32 + lane * 3 + 2] = aV02;
        out[n1 * 128 + lane] = accS1;
        out[n1 * 128 + 32 + lane * 3 + 0] = aV10;
        out[n1 * 128 + 32 + lane * 3 + 1] = aV11;
        out[n1 * 128 + 32 + lane * 3 + 2] = aV12;
    }
}

// ---------------------------------------------------------------------------
extern "C" void kernel_launch(void* const* d_in, const int* in_sizes, int n_in,
                              void* d_out, int out_size) {
    const float* node_s       = (const float*)d_in[0];
    const float* node_v       = (const float*)d_in[1];
    const float* node_attr    = (const float*)d_in[2];
    const float* edge_attr    = (const float*)d_in[3];
    const float* edge_scalars = (const float*)d_in[4];
    const float* W1_0         = (const float*)d_in[5];
    const float* W1_1         = (const float*)d_in[6];
    const float* Wfc1         = (const float*)d_in[7];
    const float* Wfc2         = (const float*)d_in[8];
    const float* W2_0         = (const float*)d_in[9];
    const float* W2_1         = (const float*)d_in[10];
    const float* Wsc0         = (const float*)d_in[11];
    const float* Wsc1         = (const float*)d_in[12];
    const int*   edge_src     = (const int*)d_in[13];
    const int*   edge_dst     = (const int*)d_in[14];
    float* out = (float*)d_out;

    cudaFuncSetAttribute(node_post4_kernel,
                         cudaFuncAttributeMaxDynamicSharedMemorySize, P4_BYTES);

    void* cnt_addr = 0;
    cudaGetSymbolAddress(&cnt_addr, g_count);
    cudaMemsetAsync(cnt_addr, 0, NN * sizeof(int));

    pre_hist_kernel<<<(NN * 32 + 255) / 256, 256>>>(node_s, node_v, W1_0, W1_1,
                                                    edge_src);
    scan_kernel<<<1, 1024>>>();
    scatter_h_kernel<<<(EE + 255) / 256, 256>>>(edge_src, edge_dst,
                                                edge_scalars, edge_attr, Wfc1);
    edge_agg4_kernel<<<NN / 4, 256>>>(Wfc2);
    node_post4_kernel<<<444, 256, P4_BYTES>>>(node_s, node_v, node_attr,
                                              W2_0, W2_1, Wsc0, Wsc1, out);
}